// round 10
// baseline (speedup 1.0000x reference)
#include <cuda_runtime.h>
#include <cuda_fp16.h>
#include <cstdint>

#define THREADS 256
#define NTILES 5
#define NCH 8

__device__ short g_pi[640];
__device__ short g_pj[640];

// smem offsets (bytes)
#define S_PAIR 0        // short pis[128], pjs[128]
#define S_XH   512      // fp16 [32][264]   16896
#define S_P    17408    // fp16 [128][264]  67584
#define S_W1   84992    // fp16 [256][136]  69632
#define S_W2   154624   // fp16 [128][136]  34816
#define S_HS   189440   // fp16 [128][136]  34816 ; reused as Ds fp32 [128][68]
#define SMEM_TOTAL 224256

__device__ __forceinline__ unsigned smem_u32(const void* p) {
    unsigned a;
    asm("{ .reg .u64 t; cvta.to.shared.u64 t, %1; cvt.u32.u64 %0, t; }" : "=r"(a) : "l"(p));
    return a;
}
__device__ __forceinline__ void ldsm4(unsigned r[4], unsigned a) {
    asm volatile("ldmatrix.sync.aligned.m8n8.x4.shared.b16 {%0,%1,%2,%3}, [%4];\n"
                 : "=r"(r[0]), "=r"(r[1]), "=r"(r[2]), "=r"(r[3]) : "r"(a));
}
__device__ __forceinline__ void ldsm4t(unsigned r[4], unsigned a) {
    asm volatile("ldmatrix.sync.aligned.m8n8.x4.trans.shared.b16 {%0,%1,%2,%3}, [%4];\n"
                 : "=r"(r[0]), "=r"(r[1]), "=r"(r[2]), "=r"(r[3]) : "r"(a));
}
__device__ __forceinline__ void mma16816(float d[4], const unsigned a[4],
                                         unsigned b0, unsigned b1) {
    asm volatile("mma.sync.aligned.m16n8k16.row.col.f32.f16.f16.f32 "
                 "{%0,%1,%2,%3}, {%4,%5,%6,%7}, {%8,%9}, {%0,%1,%2,%3};\n"
                 : "+f"(d[0]), "+f"(d[1]), "+f"(d[2]), "+f"(d[3])
                 : "r"(a[0]), "r"(a[1]), "r"(a[2]), "r"(a[3]), "r"(b0), "r"(b1));
}
__device__ __forceinline__ unsigned hmul2u(unsigned a, unsigned b) {
    __half2 r = __hmul2(*(__half2*)&a, *(__half2*)&b);
    return *(unsigned*)&r;
}
__device__ __forceinline__ unsigned f2h2u(float x, float y) {
    __half2 h = __floats2half2_rn(x, y);
    return *(unsigned*)&h;
}

__global__ void init_pairs() {
    int q = threadIdx.x;
    if (q >= 640) return;
    if (q < 528) {
        int i = 0, base = 0;
        while (base + (32 - i) <= q) { base += 32 - i; ++i; }
        g_pi[q] = (short)i;
        g_pj[q] = (short)(i + (q - base));
    } else {
        g_pi[q] = 0; g_pj[q] = 0;   // pads: built but never scattered
    }
}

__global__ __launch_bounds__(THREADS, 1)
void pairsym_kernel(const float* __restrict__ X,  const float* __restrict__ W1g,
                    const float* __restrict__ b1g, const float* __restrict__ W2g,
                    const float* __restrict__ b2g, float* __restrict__ out)
{
    extern __shared__ unsigned char smem[];
    const int b = blockIdx.x, tid = threadIdx.x;
    const int w = tid >> 5, lane = tid & 31;
    const int wm = w >> 1, wn = w & 1;          // warp grid: 4 m-rows x 2 n-cols
    const int gid = lane >> 2, tig = lane & 3;
    const int mat = lane >> 3, mr = lane & 7;
    const int lrow = (mat & 1) * 8 + mr;
    const int kh = (mat >> 1) * 8;

    const unsigned sb = smem_u32(smem);
    short* pis = (short*)(smem + S_PAIR);
    short* pjs = pis + 128;

    // ---- out init = 32*b2 (this CTA owns out[b] exclusively)
    {
        float* og = out + (size_t)b * 8192;
        for (int n = tid; n < 8192; n += THREADS)
            og[n] = 32.f * __ldg(b2g + (n & 255));
    }
    // ---- stage X_b fp16 [32][264]
    for (int q = tid; q < 1024; q += THREADS) {
        int row = q >> 5, u = q & 31;
        const float4* s = (const float4*)(X + (size_t)b * 8192 + row * 256 + u * 8);
        float4 v0 = s[0], v1 = s[1];
        *(uint4*)(smem + S_XH + row * 528 + u * 16) =
            make_uint4(f2h2u(v0.x, v0.y), f2h2u(v0.z, v0.w),
                       f2h2u(v1.x, v1.y), f2h2u(v1.z, v1.w));
    }

    // fragment base addresses (R5-proven stride classes: 264 for A-ldsm4, 136 for B-ldsm4t/A-ldsm4)
    const unsigned aP  = sb + S_P  + (unsigned)(((32 * wm + lrow) * 264 + kh) * 2);
    const unsigned aB1 = sb + S_W1 + (unsigned)((lrow * 136 + 64 * wn + kh) * 2);
    const unsigned aH  = sb + S_HS + (unsigned)(((32 * wm + lrow) * 136 + kh) * 2);
    const unsigned aB2 = sb + S_W2 + (unsigned)((lrow * 136 + 64 * wn + kh) * 2);

    float oacc[2][2][8][4];   // [d-half][m][t][r] — per-tile accumulator over chunks

    for (int tile = 0; tile < NTILES; ++tile) {
        #pragma unroll
        for (int dh = 0; dh < 2; ++dh)
            #pragma unroll
            for (int m = 0; m < 2; ++m)
                #pragma unroll
                for (int t = 0; t < 8; ++t)
                    #pragma unroll
                    for (int r = 0; r < 4; ++r) oacc[dh][m][t][r] = 0.f;

        __syncthreads();   // prev tile: P/pair readers + Ds scans done
        if (tid < 128) {
            pis[tid] = g_pi[tile * 128 + tid];
            pjs[tid] = g_pj[tile * 128 + tid];
        }
        __syncthreads();

        // ---- build P tile once: row r = pair (pi, pj): P[r,:] = xh[pi] .* xh[pj]
        {
            int r = tid >> 1, hb = tid & 1;
            int pi_ = pis[r], pj_ = pjs[r];
            const unsigned char* xi = smem + S_XH + pi_ * 528 + hb * 256;
            const unsigned char* xj = smem + S_XH + pj_ * 528 + hb * 256;
            unsigned char* pr = smem + S_P + r * 528 + hb * 256;
            #pragma unroll
            for (int u = 0; u < 16; ++u) {
                uint4 a  = *(const uint4*)(xi + u * 16);
                uint4 c2 = *(const uint4*)(xj + u * 16);
                uint4 o;
                o.x = hmul2u(a.x, c2.x); o.y = hmul2u(a.y, c2.y);
                o.z = hmul2u(a.z, c2.z); o.w = hmul2u(a.w, c2.w);
                *(uint4*)(pr + u * 16) = o;
            }
        }

        for (int c = 0; c < NCH; ++c) {
            __syncthreads();   // prev chunk readers of W1/W2/hs done; P build visible (chunk 0)
            // ---- stage W1 chunk [256 d][128 hc]
            for (int q = tid; q < 4096; q += THREADS) {
                int d = q >> 4, f = q & 15;
                const float* s = W1g + (size_t)d * 1024 + c * 128 + f * 8;
                float4 v0 = *(const float4*)s, v1 = *(const float4*)(s + 4);
                *(uint4*)(smem + S_W1 + d * 272 + f * 16) =
                    make_uint4(f2h2u(v0.x, v0.y), f2h2u(v0.z, v0.w),
                               f2h2u(v1.x, v1.y), f2h2u(v1.z, v1.w));
            }
            // ---- stage W2 chunk, d-half 0: [128 hc][128 d]
            for (int q = tid; q < 2048; q += THREADS) {
                int h = q >> 4, f = q & 15;
                const float* s = W2g + (size_t)(c * 128 + h) * 256 + f * 8;
                float4 v0 = *(const float4*)s, v1 = *(const float4*)(s + 4);
                *(uint4*)(smem + S_W2 + h * 272 + f * 16) =
                    make_uint4(f2h2u(v0.x, v0.y), f2h2u(v0.z, v0.w),
                               f2h2u(v1.x, v1.y), f2h2u(v1.z, v1.w));
            }
            __syncthreads();

            // ---- GEMM1: h[128,128] = P @ W1c ; warp: rows [32wm,+32), cols [64wn,+64)
            float hacc[2][8][4];
            #pragma unroll
            for (int m = 0; m < 2; ++m)
                #pragma unroll
                for (int t = 0; t < 8; ++t)
                    #pragma unroll
                    for (int r = 0; r < 4; ++r) hacc[m][t][r] = 0.f;
            #pragma unroll 4
            for (int kk = 0; kk < 16; ++kk) {
                unsigned A0[4], A1[4], B[16];
                ldsm4(A0, aP + (unsigned)(kk * 32));
                ldsm4(A1, aP + (unsigned)(kk * 32 + 16 * 528));
                unsigned bk = aB1 + (unsigned)(kk * 16 * 272);
                ldsm4t(B,      bk);
                ldsm4t(B + 4,  bk + 32);
                ldsm4t(B + 8,  bk + 64);
                ldsm4t(B + 12, bk + 96);
                #pragma unroll
                for (int t = 0; t < 8; ++t) {
                    mma16816(hacc[0][t], A0, B[2 * t], B[2 * t + 1]);
                    mma16816(hacc[1][t], A1, B[2 * t], B[2 * t + 1]);
                }
            }
            // ---- bias + relu -> hs fp16
            #pragma unroll
            for (int t = 0; t < 8; ++t) {
                int col = 64 * wn + 8 * t + 2 * tig;
                float bv0 = __ldg(b1g + c * 128 + col);
                float bv1 = __ldg(b1g + c * 128 + col + 1);
                #pragma unroll
                for (int m = 0; m < 2; ++m) {
                    int r0 = 32 * wm + 16 * m + gid;
                    *(unsigned*)(smem + S_HS + r0 * 272 + col * 2) =
                        f2h2u(fmaxf(hacc[m][t][0] + bv0, 0.f), fmaxf(hacc[m][t][1] + bv1, 0.f));
                    *(unsigned*)(smem + S_HS + (r0 + 8) * 272 + col * 2) =
                        f2h2u(fmaxf(hacc[m][t][2] + bv0, 0.f), fmaxf(hacc[m][t][3] + bv1, 0.f));
                }
            }
            __syncthreads();   // hs + W2 half0 visible

            // ---- GEMM2 half 0: oacc[0] += h @ W2c[:,0:128]
            #pragma unroll 2
            for (int kk = 0; kk < 8; ++kk) {
                unsigned A0[4], A1[4], B[16];
                ldsm4(A0, aH + (unsigned)(kk * 32));
                ldsm4(A1, aH + (unsigned)(kk * 32 + 16 * 272));
                unsigned bk = aB2 + (unsigned)(kk * 16 * 272);
                ldsm4t(B,      bk);
                ldsm4t(B + 4,  bk + 32);
                ldsm4t(B + 8,  bk + 64);
                ldsm4t(B + 12, bk + 96);
                #pragma unroll
                for (int t = 0; t < 8; ++t) {
                    mma16816(oacc[0][0][t], A0, B[2 * t], B[2 * t + 1]);
                    mma16816(oacc[0][1][t], A1, B[2 * t], B[2 * t + 1]);
                }
            }
            __syncthreads();   // W2s readers done
            // ---- stage W2 half 1
            for (int q = tid; q < 2048; q += THREADS) {
                int h = q >> 4, f = q & 15;
                const float* s = W2g + (size_t)(c * 128 + h) * 256 + 128 + f * 8;
                float4 v0 = *(const float4*)s, v1 = *(const float4*)(s + 4);
                *(uint4*)(smem + S_W2 + h * 272 + f * 16) =
                    make_uint4(f2h2u(v0.x, v0.y), f2h2u(v0.z, v0.w),
                               f2h2u(v1.x, v1.y), f2h2u(v1.z, v1.w));
            }
            __syncthreads();
            // ---- GEMM2 half 1: oacc[1] += h @ W2c[:,128:256]
            #pragma unroll 2
            for (int kk = 0; kk < 8; ++kk) {
                unsigned A0[4], A1[4], B[16];
                ldsm4(A0, aH + (unsigned)(kk * 32));
                ldsm4(A1, aH + (unsigned)(kk * 32 + 16 * 272));
                unsigned bk = aB2 + (unsigned)(kk * 16 * 272);
                ldsm4t(B,      bk);
                ldsm4t(B + 4,  bk + 32);
                ldsm4t(B + 8,  bk + 64);
                ldsm4t(B + 12, bk + 96);
                #pragma unroll
                for (int t = 0; t < 8; ++t) {
                    mma16816(oacc[1][0][t], A0, B[2 * t], B[2 * t + 1]);
                    mma16816(oacc[1][1][t], A1, B[2 * t], B[2 * t + 1]);
                }
            }
        }

        // ---- scatter: Dacc rows (pairs) -> out[pj] and out[pi] (i!=j), 4 passes of 64 cols
        const int sj = tid >> 3, dl = (tid & 7) * 8;
        float* Ds = (float*)(smem + S_HS);
        #pragma unroll
        for (int dh = 0; dh < 2; ++dh) {
            #pragma unroll
            for (int pw = 0; pw < 2; ++pw) {
                __syncthreads();   // hs/Ds free
                if (wn == pw) {
                    #pragma unroll
                    for (int t = 0; t < 8; ++t) {
                        int cl = 8 * t + 2 * tig;
                        #pragma unroll
                        for (int m = 0; m < 2; ++m) {
                            int r0 = 32 * wm + 16 * m + gid;
                            Ds[r0 * 68 + cl]           = oacc[dh][m][t][0];
                            Ds[r0 * 68 + cl + 1]       = oacc[dh][m][t][1];
                            Ds[(r0 + 8) * 68 + cl]     = oacc[dh][m][t][2];
                            Ds[(r0 + 8) * 68 + cl + 1] = oacc[dh][m][t][3];
                        }
                    }
                }
                __syncthreads();
                float acc[8];
                #pragma unroll
                for (int e = 0; e < 8; ++e) acc[e] = 0.f;
                for (int p = 0; p < 128; ++p) {
                    if (tile * 128 + p >= 528) break;   // uniform across CTA
                    int jp = pjs[p], ip = pis[p];
                    if (jp == sj || (ip == sj && ip != jp)) {
                        float4 v0 = *(const float4*)(Ds + p * 68 + dl);
                        float4 v1 = *(const float4*)(Ds + p * 68 + dl + 4);
                        acc[0] += v0.x; acc[1] += v0.y; acc[2] += v0.z; acc[3] += v0.w;
                        acc[4] += v1.x; acc[5] += v1.y; acc[6] += v1.z; acc[7] += v1.w;
                    }
                }
                float* og = out + (size_t)b * 8192 + sj * 256 + dh * 128 + pw * 64 + dl;
                float4 o0 = *(float4*)og, o1 = *(float4*)(og + 4);
                o0.x += acc[0]; o0.y += acc[1]; o0.z += acc[2]; o0.w += acc[3];
                o1.x += acc[4]; o1.y += acc[5]; o1.z += acc[6]; o1.w += acc[7];
                *(float4*)og = o0; *(float4*)(og + 4) = o1;
            }
        }
    }
}

extern "C" void kernel_launch(void* const* d_in, const int* in_sizes, int n_in,
                              void* d_out, int out_size) {
    (void)in_sizes; (void)n_in; (void)out_size;
    const float* X  = (const float*)d_in[0];   // [128,32,256]
    const float* W1 = (const float*)d_in[1];   // [256,1024]
    const float* b1 = (const float*)d_in[2];   // [1024]
    const float* W2 = (const float*)d_in[3];   // [1024,256]
    const float* b2 = (const float*)d_in[4];   // [256]
    float* out = (float*)d_out;                // [128,32,256]

    init_pairs<<<1, 640>>>();
    cudaFuncSetAttribute(pairsym_kernel,
                         cudaFuncAttributeMaxDynamicSharedMemorySize, SMEM_TOTAL);
    pairsym_kernel<<<128, THREADS, SMEM_TOTAL>>>(X, W1, b1, W2, b2, out);
}

// round 11
// speedup vs baseline: 1.5106x; 1.5106x over previous
#include <cuda_runtime.h>
#include <cuda_fp16.h>
#include <cstdint>

#define NDIM   32
#define DDIM   256
#define HDIM   1024
#define HC     128
#define NCHUNK 8
#define THREADS 384
#define NGROUP 3

// strides in halves (R5-proven conflict-free classes)
#define XH_H 264
#define PS_H 264
#define W1_H 136
#define W2_H 264
#define HS_H 136

// byte offsets
#define S_XH  0                      // fp16 [32][264]            16896
#define S_PS  16896                  // 3 x fp16 [32][264]        50688
#define PS_BUF 16896
#define S_W1  67584                  // fp16 [256][136]           69632
#define S_W2  137216                 // fp16 [128][264]           67584
#define S_HS  204800                 // 3 x fp16 [32][136]        26112
#define HS_BUF 8704
#define SMEM_TOTAL 230912            // <= 227KB opt-in

__device__ __forceinline__ unsigned smem_u32(const void* p) {
    unsigned a;
    asm("{ .reg .u64 t; cvta.to.shared.u64 t, %1; cvt.u32.u64 %0, t; }" : "=r"(a) : "l"(p));
    return a;
}
__device__ __forceinline__ void ldsm4(unsigned r[4], unsigned a) {
    asm volatile("ldmatrix.sync.aligned.m8n8.x4.shared.b16 {%0,%1,%2,%3}, [%4];\n"
                 : "=r"(r[0]), "=r"(r[1]), "=r"(r[2]), "=r"(r[3]) : "r"(a));
}
__device__ __forceinline__ void ldsm4t(unsigned r[4], unsigned a) {
    asm volatile("ldmatrix.sync.aligned.m8n8.x4.trans.shared.b16 {%0,%1,%2,%3}, [%4];\n"
                 : "=r"(r[0]), "=r"(r[1]), "=r"(r[2]), "=r"(r[3]) : "r"(a));
}
__device__ __forceinline__ void mma16816(float d[4], const unsigned a[4],
                                         unsigned b0, unsigned b1) {
    asm volatile("mma.sync.aligned.m16n8k16.row.col.f32.f16.f16.f32 "
                 "{%0,%1,%2,%3}, {%4,%5,%6,%7}, {%8,%9}, {%0,%1,%2,%3};\n"
                 : "+f"(d[0]), "+f"(d[1]), "+f"(d[2]), "+f"(d[3])
                 : "r"(a[0]), "r"(a[1]), "r"(a[2]), "r"(a[3]), "r"(b0), "r"(b1));
}
__device__ __forceinline__ unsigned hmul2u(unsigned a, unsigned b) {
    __half2 r = __hmul2(*(__half2*)&a, *(__half2*)&b);
    return *(unsigned*)&r;
}
__device__ __forceinline__ unsigned f2h2u(float x, float y) {
    __half2 h = __floats2half2_rn(x, y);
    return *(unsigned*)&h;
}

__global__ __launch_bounds__(THREADS, 1)
void fused_pair_mlp_v6(const float* __restrict__ X,  const float* __restrict__ W1g,
                       const float* __restrict__ b1g, const float* __restrict__ W2g,
                       const float* __restrict__ b2g, float* __restrict__ out)
{
    extern __shared__ unsigned char smem[];
    const int b = blockIdx.x, tid = threadIdx.x;
    const int w = tid >> 5, lane = tid & 31;
    const int g = w >> 2;          // 3 groups of 4 warps
    const int wg = w & 3;
    const int gtid = tid & 127;    // thread-in-group
    const int gid = lane >> 2, tig = lane & 3;

    unsigned char* Psp = smem + S_PS + g * PS_BUF;
    unsigned char* W1p = smem + S_W1;
    unsigned char* W2p = smem + S_W2;
    unsigned char* Hsp = smem + S_HS + g * HS_BUF;

    // ---- stage X_b as fp16 [32][264]
    for (int q = tid; q < 1024; q += THREADS) {
        int row = q >> 5, u = q & 31;
        const float4* s = (const float4*)(X + (size_t)b * 8192 + row * 256 + u * 8);
        float4 v0 = s[0], v1 = s[1];
        *(uint4*)(smem + S_XH + row * 528 + u * 16) =
            make_uint4(f2h2u(v0.x, v0.y), f2h2u(v0.z, v0.w),
                       f2h2u(v1.x, v1.y), f2h2u(v1.z, v1.w));
    }

    // ldmatrix per-lane address components (R5-identical)
    const int mat  = lane >> 3, mr = lane & 7;
    const int lrow = (mat & 1) * 8 + mr;
    const int kh   = (mat >> 1) * 8;

    const unsigned aA  = smem_u32(Psp) + (unsigned)(lrow * PS_H + kh) * 2u;
    const unsigned aB1 = smem_u32(W1p) + (unsigned)(lrow * W1_H + 32 * wg + kh) * 2u;
    const unsigned aH  = smem_u32(Hsp) + (unsigned)(lrow * HS_H + kh) * 2u;
    const unsigned aB2 = smem_u32(W2p) + (unsigned)(lrow * W2_H + 64 * wg + kh) * 2u;

    // P-build mapping: thread -> (row pj, strided 16B units seg+4u'')
    const int pj = gtid >> 2, seg = gtid & 3;

    // persistent out accumulator: warp owns out cols [64wg, 64wg+64)
    float oacc[2][8][4];
    #pragma unroll
    for (int m = 0; m < 2; ++m)
        #pragma unroll
        for (int t = 0; t < 8; ++t)
            #pragma unroll
            for (int r = 0; r < 4; ++r) oacc[m][t][r] = 0.f;

    for (int c = 0; c < NCHUNK; ++c) {
        __syncthreads();  // all readers of previous W chunk done

        // stage W1 chunk [256 d x 128 hc] -> half, stride 136
        for (int q = tid; q < 8192; q += THREADS) {
            int d = q >> 5, f = q & 31;
            float4 v = *(const float4*)(W1g + (size_t)d * HDIM + c * HC + f * 4);
            *(uint2*)(W1p + d * 272 + f * 8) =
                make_uint2(f2h2u(v.x, v.y), f2h2u(v.z, v.w));
        }
        // stage W2 chunk [128 hc x 256 d] -> half, stride 264
        for (int q = tid; q < 8192; q += THREADS) {
            int h = q >> 6, f = q & 63;
            float4 v = *(const float4*)(W2g + (size_t)(c * HC + h) * DDIM + f * 4);
            *(uint2*)(W2p + h * 528 + f * 8) =
                make_uint2(f2h2u(v.x, v.y), f2h2u(v.z, v.w));
        }
        float b1v[4][2];
        #pragma unroll
        for (int t = 0; t < 4; ++t) {
            b1v[t][0] = __ldg(b1g + c * HC + 32 * wg + 8 * t + 2 * tig);
            b1v[t][1] = __ldg(b1g + c * HC + 32 * wg + 8 * t + 2 * tig + 1);
        }
        __syncthreads();  // W chunk ready

        for (int ii = 0; ii < 11; ++ii) {
            const int i = NGROUP * ii + g;   // group-private i stream
            if (i < NDIM) {
                // ---- build P_i[j,:] = xh[j] .* xh[i]  (strided 16B units)
                {
                    const unsigned char* xj = smem + S_XH + pj * 528;
                    const unsigned char* xi = smem + S_XH + i * 528;
                    unsigned char* pd = Psp + pj * 528;
                    #pragma unroll
                    for (int u2 = 0; u2 < 8; ++u2) {
                        int u = seg + 4 * u2;
                        uint4 a  = *(const uint4*)(xj + u * 16);
                        uint4 c2 = *(const uint4*)(xi + u * 16);
                        uint4 o;
                        o.x = hmul2u(a.x, c2.x); o.y = hmul2u(a.y, c2.y);
                        o.z = hmul2u(a.z, c2.z); o.w = hmul2u(a.w, c2.w);
                        *(uint4*)(pd + u * 16) = o;
                    }
                }
                asm volatile("bar.sync %0, %1;" :: "r"(1 + g), "r"(128));  // P ready

                // ---- GEMM1: h[32, 32wg..+32] = P[32,256] @ W1[256, chunk]
                float hacc[2][4][4];
                #pragma unroll
                for (int m = 0; m < 2; ++m)
                    #pragma unroll
                    for (int t = 0; t < 4; ++t)
                        #pragma unroll
                        for (int r = 0; r < 4; ++r) hacc[m][t][r] = 0.f;
                #pragma unroll 2
                for (int kk = 0; kk < 16; ++kk) {
                    unsigned A0[4], A1[4], B[8];
                    unsigned ak = aA + (unsigned)(kk * 32);
                    ldsm4(A0, ak);
                    ldsm4(A1, ak + (unsigned)(16 * 528));
                    unsigned bk = aB1 + (unsigned)(kk * 16 * 272);
                    ldsm4t(B, bk);
                    ldsm4t(B + 4, bk + 32);
                    #pragma unroll
                    for (int t = 0; t < 4; ++t) {
                        mma16816(hacc[0][t], A0, B[2 * t], B[2 * t + 1]);
                        mma16816(hacc[1][t], A1, B[2 * t], B[2 * t + 1]);
                    }
                }

                // ---- bias + relu -> Hs (single buffer; safe by barrier order)
                #pragma unroll
                for (int m = 0; m < 2; ++m) {
                    #pragma unroll
                    for (int t = 0; t < 4; ++t) {
                        int col = 32 * wg + 8 * t + 2 * tig;
                        float f0 = fmaxf(hacc[m][t][0] + b1v[t][0], 0.f);
                        float f1 = fmaxf(hacc[m][t][1] + b1v[t][1], 0.f);
                        float f2 = fmaxf(hacc[m][t][2] + b1v[t][0], 0.f);
                        float f3 = fmaxf(hacc[m][t][3] + b1v[t][1], 0.f);
                        int r0 = 16 * m + gid;
                        *(unsigned*)(Hsp + r0 * 272 + col * 2)       = f2h2u(f0, f1);
                        *(unsigned*)(Hsp + (r0 + 8) * 272 + col * 2) = f2h2u(f2, f3);
                    }
                }
                asm volatile("bar.sync %0, %1;" :: "r"(1 + g), "r"(128));  // Hs ready

                // ---- GEMM2: oacc[32, 64wg..] += h[32,128] @ W2[128,256]
                #pragma unroll 2
                for (int kk = 0; kk < 8; ++kk) {
                    unsigned A0[4], A1[4], B[8];
                    unsigned ak = aH + (unsigned)(kk * 32);
                    ldsm4(A0, ak);
                    ldsm4(A1, ak + (unsigned)(16 * 272));
                    unsigned bk = aB2 + (unsigned)(kk * 16 * 528);
                    ldsm4t(B, bk);
                    ldsm4t(B + 4, bk + 32);
                    #pragma unroll
                    for (int t = 0; t < 4; ++t) {
                        mma16816(oacc[0][t], A0, B[2 * t], B[2 * t + 1]);
                        mma16816(oacc[1][t], A1, B[2 * t], B[2 * t + 1]);
                    }
                    ldsm4t(B, bk + 64);
                    ldsm4t(B + 4, bk + 96);
                    #pragma unroll
                    for (int t = 0; t < 4; ++t) {
                        mma16816(oacc[0][t + 4], A0, B[2 * t], B[2 * t + 1]);
                        mma16816(oacc[1][t + 4], A1, B[2 * t], B[2 * t + 1]);
                    }
                }
            }
        }
    }

    // ---- epilogue: groups 1,2 dump to smem; group 0 reduces + bias + store
    __syncthreads();
    if (g > 0) {
        float* Os = (float*)(smem + (g - 1) * 32768);   // X/P regions dead
        #pragma unroll
        for (int t = 0; t < 8; ++t) {
            int col = 64 * wg + 8 * t + 2 * tig;
            #pragma unroll
            for (int m = 0; m < 2; ++m) {
                int r0 = 16 * m + gid;
                *(float2*)(Os + r0 * DDIM + col)       = make_float2(oacc[m][t][0], oacc[m][t][1]);
                *(float2*)(Os + (r0 + 8) * DDIM + col) = make_float2(oacc[m][t][2], oacc[m][t][3]);
            }
        }
    }
    __syncthreads();
    if (g == 0) {
        float* Os1 = (float*)(smem);
        float* Os2 = (float*)(smem + 32768);
        float* og = out + (size_t)b * NDIM * DDIM;
        #pragma unroll
        for (int t = 0; t < 8; ++t) {
            int col = 64 * wg + 8 * t + 2 * tig;
            float bb0 = 32.0f * __ldg(b2g + col);
            float bb1 = 32.0f * __ldg(b2g + col + 1);
            #pragma unroll
            for (int m = 0; m < 2; ++m) {
                int r0 = 16 * m + gid;
                float2 s0 = *(float2*)(Os1 + r0 * DDIM + col);
                float2 s1 = *(float2*)(Os1 + (r0 + 8) * DDIM + col);
                float2 u0 = *(float2*)(Os2 + r0 * DDIM + col);
                float2 u1 = *(float2*)(Os2 + (r0 + 8) * DDIM + col);
                *(float2*)(og + (size_t)r0 * DDIM + col) =
                    make_float2(oacc[m][t][0] + s0.x + u0.x + bb0,
                                oacc[m][t][1] + s0.y + u0.y + bb1);
                *(float2*)(og + (size_t)(r0 + 8) * DDIM + col) =
                    make_float2(oacc[m][t][2] + s1.x + u1.x + bb0,
                                oacc[m][t][3] + s1.y + u1.y + bb1);
            }
        }
    }
}

extern "C" void kernel_launch(void* const* d_in, const int* in_sizes, int n_in,
                              void* d_out, int out_size) {
    (void)in_sizes; (void)n_in; (void)out_size;
    const float* X  = (const float*)d_in[0];   // [128,32,256]
    const float* W1 = (const float*)d_in[1];   // [256,1024]
    const float* b1 = (const float*)d_in[2];   // [1024]
    const float* W2 = (const float*)d_in[3];   // [1024,256]
    const float* b2 = (const float*)d_in[4];   // [256]
    float* out = (float*)d_out;                // [128,32,256]

    cudaFuncSetAttribute(fused_pair_mlp_v6,
                         cudaFuncAttributeMaxDynamicSharedMemorySize, SMEM_TOTAL);
    fused_pair_mlp_v6<<<128, THREADS, SMEM_TOTAL>>>(X, W1, b1, W2, b2, out);
}